// round 1
// baseline (speedup 1.0000x reference)
#include <cuda_runtime.h>
#include <cuda_bf16.h>
#include <math.h>

// Problem constants (shape-specialized)
#define BB   2
#define SS   2048
#define DD   1024
#define HH   16
#define HD   64
#define DFF  4096
#define WIN  128
#define MTOT (BB * SS)          // 4096 rows

// ---------------- scratch (static __device__, no allocation) ----------------
__device__ float g_qkv[(size_t)MTOT * 3 * DD];   // (B,S,3D)  50 MB
__device__ float g_attn[(size_t)MTOT * DD];      // attn heads->(B,S,D)
__device__ float g_tmp[(size_t)MTOT * DD];       // proj / ff2 output
__device__ float g_x2[(size_t)MTOT * DD];        // after ln1
__device__ float g_ff[(size_t)MTOT * DFF];       // relu(ff1)  67 MB

// ---------------- GEMM: C[M,N] = A[M,K] @ B[N,K]^T + bias, optional ReLU ----
// BM=BN=128, BK=16, 256 threads, 8x8 register tile per thread.
template<bool RELU>
__global__ __launch_bounds__(256)
void gemm_tn(const float* __restrict__ A, const float* __restrict__ B,
             const float* __restrict__ bias, float* __restrict__ C,
             int M, int N, int K)
{
    __shared__ float As[16][132];
    __shared__ float Bs[16][132];

    const int bx = blockIdx.x;       // N tile
    const int by = blockIdx.y;       // M tile
    const int tid = threadIdx.x;

    const int tx = tid & 15;         // 0..15 -> 8 output cols
    const int ty = tid >> 4;         // 0..15 -> 8 output rows

    const int lrow = tid >> 2;       // 0..63
    const int lcol = (tid & 3) << 2; // 0,4,8,12

    const float* Abase = A + (size_t)(by * 128) * K;
    const float* Bbase = B + (size_t)(bx * 128) * K;

    float acc[8][8];
#pragma unroll
    for (int i = 0; i < 8; i++)
#pragma unroll
        for (int j = 0; j < 8; j++) acc[i][j] = 0.f;

    for (int k0 = 0; k0 < K; k0 += 16) {
#pragma unroll
        for (int i = 0; i < 2; i++) {
            int r = lrow + i * 64;
            float4 va = *(const float4*)(Abase + (size_t)r * K + k0 + lcol);
            As[lcol + 0][r] = va.x; As[lcol + 1][r] = va.y;
            As[lcol + 2][r] = va.z; As[lcol + 3][r] = va.w;
            float4 vb = *(const float4*)(Bbase + (size_t)r * K + k0 + lcol);
            Bs[lcol + 0][r] = vb.x; Bs[lcol + 1][r] = vb.y;
            Bs[lcol + 2][r] = vb.z; Bs[lcol + 3][r] = vb.w;
        }
        __syncthreads();

#pragma unroll
        for (int kk = 0; kk < 16; kk++) {
            float a[8], b[8];
            *(float4*)&a[0] = *(const float4*)&As[kk][ty * 8];
            *(float4*)&a[4] = *(const float4*)&As[kk][ty * 8 + 4];
            *(float4*)&b[0] = *(const float4*)&Bs[kk][tx * 8];
            *(float4*)&b[4] = *(const float4*)&Bs[kk][tx * 8 + 4];
#pragma unroll
            for (int i = 0; i < 8; i++)
#pragma unroll
                for (int j = 0; j < 8; j++)
                    acc[i][j] = fmaf(a[i], b[j], acc[i][j]);
        }
        __syncthreads();
    }

    // epilogue
    float bvals[8];
#pragma unroll
    for (int j = 0; j < 8; j++) bvals[j] = bias[bx * 128 + tx * 8 + j];

    float* Cb = C + (size_t)(by * 128 + ty * 8) * N + bx * 128 + tx * 8;
#pragma unroll
    for (int i = 0; i < 8; i++) {
        float4 o0, o1;
        float v;
        v = acc[i][0] + bvals[0]; o0.x = RELU ? fmaxf(v, 0.f) : v;
        v = acc[i][1] + bvals[1]; o0.y = RELU ? fmaxf(v, 0.f) : v;
        v = acc[i][2] + bvals[2]; o0.z = RELU ? fmaxf(v, 0.f) : v;
        v = acc[i][3] + bvals[3]; o0.w = RELU ? fmaxf(v, 0.f) : v;
        v = acc[i][4] + bvals[4]; o1.x = RELU ? fmaxf(v, 0.f) : v;
        v = acc[i][5] + bvals[5]; o1.y = RELU ? fmaxf(v, 0.f) : v;
        v = acc[i][6] + bvals[6]; o1.z = RELU ? fmaxf(v, 0.f) : v;
        v = acc[i][7] + bvals[7]; o1.w = RELU ? fmaxf(v, 0.f) : v;
        *(float4*)(Cb + (size_t)i * N)     = o0;
        *(float4*)(Cb + (size_t)i * N + 4) = o1;
    }
}

// ---------------- banded flash attention ----------------
// grid: (S/32, H, B), block: 1024 threads (32 warps, one warp = one query).
// Reads Q,K,V from g_qkv (B,S,3D); writes (B,S,D)-layout attn output.
__global__ __launch_bounds__(1024)
void attn_kernel(const float* __restrict__ qkv, float* __restrict__ attn_out)
{
    const int b  = blockIdx.z;
    const int h  = blockIdx.y;
    const int q0 = blockIdx.x * 32;
    const int warp = threadIdx.x >> 5;
    const int lane = threadIdx.x & 31;
    const int q = q0 + warp;

    const float* base = qkv + (size_t)b * SS * (3 * DD);
    const int hc = h * HD;

    const float q0r = base[(size_t)q * (3 * DD) + hc + lane];
    const float q1r = base[(size_t)q * (3 * DD) + hc + lane + 32];

    const int klo = max(q0 - WIN, 0);
    const int khi = min(q0 + 31 + WIN, SS - 1);

    __shared__ float Ks[32][64];
    __shared__ float Vs[32][64];

    float m = -1e30f, lsum = 0.f, acc0 = 0.f, acc1 = 0.f;

    for (int c = klo; c <= khi; c += 32) {
        const int nk = min(32, khi - c + 1);
        __syncthreads();
        for (int idx = threadIdx.x; idx < nk * 64; idx += 1024) {
            int j = idx >> 6, d = idx & 63;
            size_t row = (size_t)(c + j) * (3 * DD);
            Ks[j][d] = base[row + DD + hc + d];
            Vs[j][d] = base[row + 2 * DD + hc + d];
        }
        __syncthreads();

        const int jlo = max(q - WIN, c) - c;
        const int jhi = min(q + WIN, c + nk - 1) - c;
        for (int j = jlo; j <= jhi; j++) {
            float partial = q0r * Ks[j][lane] + q1r * Ks[j][lane + 32];
#pragma unroll
            for (int off = 16; off > 0; off >>= 1)
                partial += __shfl_xor_sync(0xFFFFFFFFu, partial, off);
            float s = partial * 0.125f;     // 1/sqrt(64)
            float nm = fmaxf(m, s);
            float scale = __expf(m - nm);
            float p = __expf(s - nm);
            lsum = lsum * scale + p;
            acc0 = acc0 * scale + p * Vs[j][lane];
            acc1 = acc1 * scale + p * Vs[j][lane + 32];
            m = nm;
        }
    }

    const float inv = 1.f / lsum;
    float* orow = attn_out + ((size_t)b * SS + q) * DD + hc;
    orow[lane]      = acc0 * inv;
    orow[lane + 32] = acc1 * inv;
}

// ---------------- fused residual + LayerNorm ----------------
// out[row] = LN(A[row] + R[row]) ; one block per row, 256 threads, D=1024.
__global__ __launch_bounds__(256)
void ln_kernel(const float* __restrict__ A, const float* __restrict__ R,
               const float* __restrict__ g, const float* __restrict__ be,
               float* __restrict__ out)
{
    const int row = blockIdx.x;
    const int t = threadIdx.x;
    const size_t base = (size_t)row * DD;

    float4 av = *(const float4*)(A + base + t * 4);
    float4 rv = *(const float4*)(R + base + t * 4);
    float4 v = make_float4(av.x + rv.x, av.y + rv.y, av.z + rv.z, av.w + rv.w);

    float s = v.x + v.y + v.z + v.w;
    float q = v.x * v.x + v.y * v.y + v.z * v.z + v.w * v.w;
#pragma unroll
    for (int off = 16; off > 0; off >>= 1) {
        s += __shfl_xor_sync(0xFFFFFFFFu, s, off);
        q += __shfl_xor_sync(0xFFFFFFFFu, q, off);
    }
    __shared__ float ss[8], sq[8];
    __shared__ float mu_s, inv_s;
    if ((t & 31) == 0) { ss[t >> 5] = s; sq[t >> 5] = q; }
    __syncthreads();
    if (t == 0) {
        float S = 0.f, Q = 0.f;
#pragma unroll
        for (int i = 0; i < 8; i++) { S += ss[i]; Q += sq[i]; }
        float mu = S * (1.f / DD);
        float var = Q * (1.f / DD) - mu * mu;
        mu_s = mu;
        inv_s = rsqrtf(var + 1e-5f);
    }
    __syncthreads();
    const float mu = mu_s, inv = inv_s;

    float4 gv = *(const float4*)(g + t * 4);
    float4 bv = *(const float4*)(be + t * 4);
    float4 o;
    o.x = (v.x - mu) * inv * gv.x + bv.x;
    o.y = (v.y - mu) * inv * gv.y + bv.y;
    o.z = (v.z - mu) * inv * gv.z + bv.z;
    o.w = (v.w - mu) * inv * gv.w + bv.w;
    *(float4*)(out + base + t * 4) = o;
}

// ---------------- host launch ----------------
extern "C" void kernel_launch(void* const* d_in, const int* in_sizes, int n_in,
                              void* d_out, int out_size)
{
    (void)in_sizes; (void)n_in; (void)out_size;
    const float* x     = (const float*)d_in[0];
    const float* in_w  = (const float*)d_in[1];
    const float* in_b  = (const float*)d_in[2];
    const float* out_w = (const float*)d_in[3];
    const float* out_b = (const float*)d_in[4];
    const float* ln1g  = (const float*)d_in[5];
    const float* ln1b  = (const float*)d_in[6];
    const float* w1    = (const float*)d_in[7];
    const float* b1    = (const float*)d_in[8];
    const float* w2    = (const float*)d_in[9];
    const float* b2    = (const float*)d_in[10];
    const float* ln2g  = (const float*)d_in[11];
    const float* ln2b  = (const float*)d_in[12];
    float* out = (float*)d_out;

    float *qkv, *attn, *tmp, *x2, *ff;
    cudaGetSymbolAddress((void**)&qkv,  g_qkv);
    cudaGetSymbolAddress((void**)&attn, g_attn);
    cudaGetSymbolAddress((void**)&tmp,  g_tmp);
    cudaGetSymbolAddress((void**)&x2,   g_x2);
    cudaGetSymbolAddress((void**)&ff,   g_ff);

    // 1. QKV projection: (4096,1024) @ (3072,1024)^T -> (4096,3072)
    gemm_tn<false><<<dim3(3 * DD / 128, MTOT / 128), 256>>>(x, in_w, in_b, qkv, MTOT, 3 * DD, DD);
    // 2. banded attention -> (B,S,D)
    attn_kernel<<<dim3(SS / 32, HH, BB), 1024>>>(qkv, attn);
    // 3. out_proj
    gemm_tn<false><<<dim3(DD / 128, MTOT / 128), 256>>>(attn, out_w, out_b, tmp, MTOT, DD, DD);
    // 4. x2 = LN(x + attn_proj)
    ln_kernel<<<MTOT, 256>>>(x, tmp, ln1g, ln1b, x2);
    // 5. ff hidden = relu(x2 @ w1^T + b1)
    gemm_tn<true><<<dim3(DFF / 128, MTOT / 128), 256>>>(x2, w1, b1, ff, MTOT, DFF, DD);
    // 6. ff out
    gemm_tn<false><<<dim3(DD / 128, MTOT / 128), 256>>>(ff, w2, b2, tmp, MTOT, DD, DFF);
    // 7. out = LN(x2 + ff_out)
    ln_kernel<<<MTOT, 256>>>(x2, tmp, ln2g, ln2b, out);
}

// round 3
// speedup vs baseline: 1.6835x; 1.6835x over previous
#include <cuda_runtime.h>
#include <cuda_bf16.h>
#include <math.h>
#include <stdint.h>

#define BB   2
#define SS   2048
#define DD   1024
#define HH   16
#define HD   64
#define DFF  4096
#define WIN  128
#define MTOT (BB * SS)

typedef __nv_bfloat16 bf16;

// ---------------- device scratch ----------------
__device__ float g_qkv[(size_t)MTOT * 3 * DD];
__device__ float g_tmp[(size_t)MTOT * DD];
__device__ float g_x2 [(size_t)MTOT * DD];
__device__ bf16 g_x_hi  [(size_t)MTOT * DD],  g_x_mid [(size_t)MTOT * DD];
__device__ bf16 g_inw_hi[(size_t)3*DD*DD],    g_inw_mid[(size_t)3*DD*DD];
__device__ bf16 g_outw_hi[(size_t)DD*DD],     g_outw_mid[(size_t)DD*DD];
__device__ bf16 g_w1_hi [(size_t)DFF*DD],     g_w1_mid[(size_t)DFF*DD];
__device__ bf16 g_w2_hi [(size_t)DD*DFF],     g_w2_mid[(size_t)DD*DFF];
__device__ bf16 g_attn_hi[(size_t)MTOT*DD],   g_attn_mid[(size_t)MTOT*DD];
__device__ bf16 g_x2_hi [(size_t)MTOT*DD],    g_x2_mid[(size_t)MTOT*DD];
__device__ bf16 g_ff_hi [(size_t)MTOT*DFF],   g_ff_mid[(size_t)MTOT*DFF];

// ---------------- low-level helpers (arch-agnostic PTX only) ----------------
__device__ __forceinline__ uint32_t smem_u32(const void* p) {
    uint32_t a;
    asm("{ .reg .u64 t; cvta.to.shared.u64 t, %1; cvt.u32.u64 %0, t; }" : "=r"(a) : "l"(p));
    return a;
}
__device__ __forceinline__ void cp16(uint32_t dst, const void* src) {
    asm volatile("cp.async.cg.shared.global [%0], [%1], 16;" :: "r"(dst), "l"(src));
}
__device__ __forceinline__ void cp_commit() {
    asm volatile("cp.async.commit_group;" ::: "memory");
}
template<int N>
__device__ __forceinline__ void cp_wait() {
    asm volatile("cp.async.wait_group %0;" :: "n"(N) : "memory");
}
__device__ __forceinline__ void mma_bf16(float& c0, float& c1, float& c2, float& c3,
                                         uint32_t a0, uint32_t a1, uint32_t a2, uint32_t a3,
                                         uint32_t b0, uint32_t b1) {
    asm volatile(
        "mma.sync.aligned.m16n8k16.row.col.f32.bf16.bf16.f32 "
        "{%0,%1,%2,%3}, {%4,%5,%6,%7}, {%8,%9}, {%0,%1,%2,%3};"
        : "+f"(c0), "+f"(c1), "+f"(c2), "+f"(c3)
        : "r"(a0), "r"(a1), "r"(a2), "r"(a3), "r"(b0), "r"(b1));
}

// ---------------- bf16x3 GEMM via mma.sync ----------------
// C[M,N] = A[M,K] @ B[N,K]^T + bias.  A,B are bf16 hi/mid splits.
// Block 128x128, BK=32, 256 thr, warp grid 2(m)x4(n), warp tile 64x32.
// Smem rows padded to 40 bf16 (80B) -> conflict-free fragment loads.
#define PITCH   40
#define MAT_E   (128 * PITCH)          // 5120 elems per matrix tile
#define STAGE_E (4 * MAT_E)            // As_hi, As_mid, Bs_hi, Bs_mid
#define GEMM_SMEM (2 * STAGE_E * 2)    // bytes: 81920

template<bool RELU, bool WF32, bool WSPLIT>
__global__ __launch_bounds__(256, 1)
void gemm_bf16x3(const bf16* __restrict__ Ahi, const bf16* __restrict__ Amid,
                 const bf16* __restrict__ Bhi, const bf16* __restrict__ Bmid,
                 const float* __restrict__ bias,
                 float* __restrict__ C, bf16* __restrict__ Chi, bf16* __restrict__ Cmid,
                 int M, int N, int K)
{
    extern __shared__ __align__(16) bf16 sm[];
    const uint32_t sbase = smem_u32(sm);
    const int tid  = threadIdx.x;
    const int warp = tid >> 5, lane = tid & 31;
    const int gid  = lane >> 2, tig = lane & 3;
    const int wm   = warp >> 2;          // 0..1
    const int wn   = warp & 3;           // 0..3
    const int bx = blockIdx.x, by = blockIdx.y;

    const size_t Abase = (size_t)(by * 128) * K;
    const size_t Bbase = (size_t)(bx * 128) * K;

    // async stage loader: 2048 16B chunks, 8 per thread
    auto load_stage = [&](int chunk, int s) {
        const int k0 = chunk * 32;
        const uint32_t sb = sbase + s * (STAGE_E * 2);
#pragma unroll
        for (int i = 0; i < 8; i++) {
            int idx = i * 256 + tid;
            int mat = idx >> 9;
            int rem = idx & 511;
            int r = rem >> 2, c16 = rem & 3;
            uint32_t dst = sb + (uint32_t)(mat * MAT_E + r * PITCH + c16 * 8) * 2;
            const bf16* srcp;
            size_t go;
            if (mat < 2) { srcp = (mat == 0) ? Ahi : Amid; go = Abase + (size_t)r * K + k0 + c16 * 8; }
            else         { srcp = (mat == 2) ? Bhi : Bmid; go = Bbase + (size_t)r * K + k0 + c16 * 8; }
            cp16(dst, srcp + go);
        }
        cp_commit();
    };

    float acc[4][4][4];
#pragma unroll
    for (int i = 0; i < 4; i++)
#pragma unroll
        for (int j = 0; j < 4; j++)
#pragma unroll
            for (int v = 0; v < 4; v++) acc[i][j][v] = 0.f;

    const int nch = K >> 5;
    load_stage(0, 0);

    for (int c = 0; c < nch; c++) {
        const int s = c & 1;
        if (c + 1 < nch) { load_stage(c + 1, s ^ 1); cp_wait<1>(); }
        else             { cp_wait<0>(); }
        __syncthreads();

        const bf16* As_h = sm + s * STAGE_E;
        const bf16* As_m = As_h + MAT_E;
        const bf16* Bs_h = As_h + 2 * MAT_E;
        const bf16* Bs_m = As_h + 3 * MAT_E;

#pragma unroll
        for (int kk = 0; kk < 32; kk += 16) {
            uint32_t ah[4][4], am[4][4], bh[4][2], bm[4][2];
#pragma unroll
            for (int mt = 0; mt < 4; mt++) {
                int r0 = wm * 64 + mt * 16 + gid;
                int kc = kk + tig * 2;
                ah[mt][0] = *(const uint32_t*)&As_h[r0 * PITCH + kc];
                ah[mt][1] = *(const uint32_t*)&As_h[(r0 + 8) * PITCH + kc];
                ah[mt][2] = *(const uint32_t*)&As_h[r0 * PITCH + kc + 8];
                ah[mt][3] = *(const uint32_t*)&As_h[(r0 + 8) * PITCH + kc + 8];
                am[mt][0] = *(const uint32_t*)&As_m[r0 * PITCH + kc];
                am[mt][1] = *(const uint32_t*)&As_m[(r0 + 8) * PITCH + kc];
                am[mt][2] = *(const uint32_t*)&As_m[r0 * PITCH + kc + 8];
                am[mt][3] = *(const uint32_t*)&As_m[(r0 + 8) * PITCH + kc + 8];
            }
#pragma unroll
            for (int nt = 0; nt < 4; nt++) {
                int n0 = wn * 32 + nt * 8 + gid;
                int kc = kk + tig * 2;
                bh[nt][0] = *(const uint32_t*)&Bs_h[n0 * PITCH + kc];
                bh[nt][1] = *(const uint32_t*)&Bs_h[n0 * PITCH + kc + 8];
                bm[nt][0] = *(const uint32_t*)&Bs_m[n0 * PITCH + kc];
                bm[nt][1] = *(const uint32_t*)&Bs_m[n0 * PITCH + kc + 8];
            }
#pragma unroll
            for (int mt = 0; mt < 4; mt++)
#pragma unroll
                for (int nt = 0; nt < 4; nt++) {
                    float* a = acc[mt][nt];
                    mma_bf16(a[0], a[1], a[2], a[3],
                             ah[mt][0], ah[mt][1], ah[mt][2], ah[mt][3],
                             bh[nt][0], bh[nt][1]);
                    mma_bf16(a[0], a[1], a[2], a[3],
                             ah[mt][0], ah[mt][1], ah[mt][2], ah[mt][3],
                             bm[nt][0], bm[nt][1]);
                    mma_bf16(a[0], a[1], a[2], a[3],
                             am[mt][0], am[mt][1], am[mt][2], am[mt][3],
                             bh[nt][0], bh[nt][1]);
                }
        }
        __syncthreads();
    }

    // epilogue
#pragma unroll
    for (int mt = 0; mt < 4; mt++) {
#pragma unroll
        for (int nt = 0; nt < 4; nt++) {
            const int col = bx * 128 + wn * 32 + nt * 8 + tig * 2;
            const float2 bv = *(const float2*)&bias[col];
            const int row0 = by * 128 + wm * 64 + mt * 16 + gid;
#pragma unroll
            for (int half = 0; half < 2; half++) {
                const int row = row0 + half * 8;
                float v0 = acc[mt][nt][half * 2]     + bv.x;
                float v1 = acc[mt][nt][half * 2 + 1] + bv.y;
                if (RELU) { v0 = fmaxf(v0, 0.f); v1 = fmaxf(v1, 0.f); }
                const size_t o = (size_t)row * N + col;
                if (WF32) *(float2*)(C + o) = make_float2(v0, v1);
                if (WSPLIT) {
                    bf16 h0 = __float2bfloat16(v0);
                    bf16 h1 = __float2bfloat16(v1);
                    __nv_bfloat162 hp; hp.x = h0; hp.y = h1;
                    __nv_bfloat162 mp;
                    mp.x = __float2bfloat16(v0 - __bfloat162float(h0));
                    mp.y = __float2bfloat16(v1 - __bfloat162float(h1));
                    *(__nv_bfloat162*)(Chi + o)  = hp;
                    *(__nv_bfloat162*)(Cmid + o) = mp;
                }
            }
        }
    }
}

// ---------------- fp32 -> (hi,mid) bf16 split ----------------
__global__ __launch_bounds__(256)
void split_kernel(const float* __restrict__ src, bf16* __restrict__ hi,
                  bf16* __restrict__ mid, int n4)
{
    int i = blockIdx.x * 256 + threadIdx.x;
    if (i >= n4) return;
    float4 v = ((const float4*)src)[i];
    bf16 h0 = __float2bfloat16(v.x), h1 = __float2bfloat16(v.y);
    bf16 h2 = __float2bfloat16(v.z), h3 = __float2bfloat16(v.w);
    __nv_bfloat162 a, b, c, d;
    a.x = h0; a.y = h1; b.x = h2; b.y = h3;
    c.x = __float2bfloat16(v.x - __bfloat162float(h0));
    c.y = __float2bfloat16(v.y - __bfloat162float(h1));
    d.x = __float2bfloat16(v.z - __bfloat162float(h2));
    d.y = __float2bfloat16(v.w - __bfloat162float(h3));
    ((__nv_bfloat162*)hi)[i*2]     = a;
    ((__nv_bfloat162*)hi)[i*2+1]   = b;
    ((__nv_bfloat162*)mid)[i*2]    = c;
    ((__nv_bfloat162*)mid)[i*2+1]  = d;
}

// ---------------- banded flash attention (fp32 in, split out) ----------------
__global__ __launch_bounds__(1024)
void attn_kernel(const float* __restrict__ qkv,
                 bf16* __restrict__ out_hi, bf16* __restrict__ out_mid)
{
    const int b  = blockIdx.z;
    const int h  = blockIdx.y;
    const int q0 = blockIdx.x * 32;
    const int warp = threadIdx.x >> 5;
    const int lane = threadIdx.x & 31;
    const int q = q0 + warp;

    const float* base = qkv + (size_t)b * SS * (3 * DD);
    const int hc = h * HD;

    const float q0r = base[(size_t)q * (3 * DD) + hc + lane];
    const float q1r = base[(size_t)q * (3 * DD) + hc + lane + 32];

    const int klo = max(q0 - WIN, 0);
    const int khi = min(q0 + 31 + WIN, SS - 1);

    __shared__ float Ks[32][64];
    __shared__ float Vs[32][64];

    float m = -1e30f, lsum = 0.f, acc0 = 0.f, acc1 = 0.f;

    for (int c = klo; c <= khi; c += 32) {
        const int nk = min(32, khi - c + 1);
        __syncthreads();
        for (int idx = threadIdx.x; idx < nk * 64; idx += 1024) {
            int j = idx >> 6, d = idx & 63;
            size_t row = (size_t)(c + j) * (3 * DD);
            Ks[j][d] = base[row + DD + hc + d];
            Vs[j][d] = base[row + 2 * DD + hc + d];
        }
        __syncthreads();

        const int jlo = max(q - WIN, c) - c;
        const int jhi = min(q + WIN, c + nk - 1) - c;
        for (int j = jlo; j <= jhi; j++) {
            float partial = q0r * Ks[j][lane] + q1r * Ks[j][lane + 32];
#pragma unroll
            for (int off = 16; off > 0; off >>= 1)
                partial += __shfl_xor_sync(0xFFFFFFFFu, partial, off);
            float s = partial * 0.125f;
            float nm = fmaxf(m, s);
            float scale = __expf(m - nm);
            float p = __expf(s - nm);
            lsum = lsum * scale + p;
            acc0 = acc0 * scale + p * Vs[j][lane];
            acc1 = acc1 * scale + p * Vs[j][lane + 32];
            m = nm;
        }
    }

    const float inv = 1.f / lsum;
    const float v0 = acc0 * inv, v1 = acc1 * inv;
    const size_t ob = ((size_t)b * SS + q) * DD + hc;
    bf16 h0 = __float2bfloat16(v0), h1 = __float2bfloat16(v1);
    out_hi[ob + lane]       = h0;
    out_hi[ob + lane + 32]  = h1;
    out_mid[ob + lane]      = __float2bfloat16(v0 - __bfloat162float(h0));
    out_mid[ob + lane + 32] = __float2bfloat16(v1 - __bfloat162float(h1));
}

// ---------------- fused residual + LayerNorm (+ optional split out) ----------------
__global__ __launch_bounds__(256)
void ln_kernel(const float* __restrict__ A, const float* __restrict__ R,
               const float* __restrict__ g, const float* __restrict__ be,
               float* __restrict__ out, bf16* __restrict__ ohi, bf16* __restrict__ omid)
{
    const int row = blockIdx.x;
    const int t = threadIdx.x;
    const size_t base = (size_t)row * DD;

    float4 av = *(const float4*)(A + base + t * 4);
    float4 rv = *(const float4*)(R + base + t * 4);
    float4 v = make_float4(av.x + rv.x, av.y + rv.y, av.z + rv.z, av.w + rv.w);

    float s = v.x + v.y + v.z + v.w;
    float q = v.x * v.x + v.y * v.y + v.z * v.z + v.w * v.w;
#pragma unroll
    for (int off = 16; off > 0; off >>= 1) {
        s += __shfl_xor_sync(0xFFFFFFFFu, s, off);
        q += __shfl_xor_sync(0xFFFFFFFFu, q, off);
    }
    __shared__ float ss[8], sq[8];
    __shared__ float mu_s, inv_s;
    if ((t & 31) == 0) { ss[t >> 5] = s; sq[t >> 5] = q; }
    __syncthreads();
    if (t == 0) {
        float S = 0.f, Q = 0.f;
#pragma unroll
        for (int i = 0; i < 8; i++) { S += ss[i]; Q += sq[i]; }
        float mu = S * (1.f / DD);
        float var = Q * (1.f / DD) - mu * mu;
        mu_s = mu;
        inv_s = rsqrtf(var + 1e-5f);
    }
    __syncthreads();
    const float mu = mu_s, inv = inv_s;

    float4 gv = *(const float4*)(g + t * 4);
    float4 bv = *(const float4*)(be + t * 4);
    float4 o;
    o.x = (v.x - mu) * inv * gv.x + bv.x;
    o.y = (v.y - mu) * inv * gv.y + bv.y;
    o.z = (v.z - mu) * inv * gv.z + bv.z;
    o.w = (v.w - mu) * inv * gv.w + bv.w;
    *(float4*)(out + base + t * 4) = o;

    if (ohi != nullptr) {
        bf16 h0 = __float2bfloat16(o.x), h1 = __float2bfloat16(o.y);
        bf16 h2 = __float2bfloat16(o.z), h3 = __float2bfloat16(o.w);
        __nv_bfloat162 p0, p1, m0, m1;
        p0.x = h0; p0.y = h1; p1.x = h2; p1.y = h3;
        m0.x = __float2bfloat16(o.x - __bfloat162float(h0));
        m0.y = __float2bfloat16(o.y - __bfloat162float(h1));
        m1.x = __float2bfloat16(o.z - __bfloat162float(h2));
        m1.y = __float2bfloat16(o.w - __bfloat162float(h3));
        *(__nv_bfloat162*)(ohi + base + t * 4)      = p0;
        *(__nv_bfloat162*)(ohi + base + t * 4 + 2)  = p1;
        *(__nv_bfloat162*)(omid + base + t * 4)     = m0;
        *(__nv_bfloat162*)(omid + base + t * 4 + 2) = m1;
    }
}

// ---------------- host ----------------
extern "C" void kernel_launch(void* const* d_in, const int* in_sizes, int n_in,
                              void* d_out, int out_size)
{
    (void)in_sizes; (void)n_in; (void)out_size;
    const float* x     = (const float*)d_in[0];
    const float* in_w  = (const float*)d_in[1];
    const float* in_b  = (const float*)d_in[2];
    const float* out_w = (const float*)d_in[3];
    const float* out_b = (const float*)d_in[4];
    const float* ln1g  = (const float*)d_in[5];
    const float* ln1b  = (const float*)d_in[6];
    const float* w1    = (const float*)d_in[7];
    const float* b1    = (const float*)d_in[8];
    const float* w2    = (const float*)d_in[9];
    const float* b2    = (const float*)d_in[10];
    const float* ln2g  = (const float*)d_in[11];
    const float* ln2b  = (const float*)d_in[12];
    float* out = (float*)d_out;

    float *qkv, *tmp, *x2;
    bf16 *xh, *xm, *inwh, *inwm, *outwh, *outwm, *w1h, *w1m, *w2h, *w2m;
    bf16 *ath, *atm, *x2h, *x2m, *ffh, *ffm;
    cudaGetSymbolAddress((void**)&qkv,   g_qkv);
    cudaGetSymbolAddress((void**)&tmp,   g_tmp);
    cudaGetSymbolAddress((void**)&x2,    g_x2);
    cudaGetSymbolAddress((void**)&xh,    g_x_hi);    cudaGetSymbolAddress((void**)&xm,    g_x_mid);
    cudaGetSymbolAddress((void**)&inwh,  g_inw_hi);  cudaGetSymbolAddress((void**)&inwm,  g_inw_mid);
    cudaGetSymbolAddress((void**)&outwh, g_outw_hi); cudaGetSymbolAddress((void**)&outwm, g_outw_mid);
    cudaGetSymbolAddress((void**)&w1h,   g_w1_hi);   cudaGetSymbolAddress((void**)&w1m,   g_w1_mid);
    cudaGetSymbolAddress((void**)&w2h,   g_w2_hi);   cudaGetSymbolAddress((void**)&w2m,   g_w2_mid);
    cudaGetSymbolAddress((void**)&ath,   g_attn_hi); cudaGetSymbolAddress((void**)&atm,   g_attn_mid);
    cudaGetSymbolAddress((void**)&x2h,   g_x2_hi);   cudaGetSymbolAddress((void**)&x2m,   g_x2_mid);
    cudaGetSymbolAddress((void**)&ffh,   g_ff_hi);   cudaGetSymbolAddress((void**)&ffm,   g_ff_mid);

    cudaFuncSetAttribute(gemm_bf16x3<false, true, false>,
                         cudaFuncAttributeMaxDynamicSharedMemorySize, GEMM_SMEM);
    cudaFuncSetAttribute(gemm_bf16x3<true, false, true>,
                         cudaFuncAttributeMaxDynamicSharedMemorySize, GEMM_SMEM);

    // splits of raw inputs
    split_kernel<<<(MTOT * DD / 4 + 255) / 256, 256>>>(x,     xh,    xm,    MTOT * DD / 4);
    split_kernel<<<(3 * DD * DD / 4 + 255) / 256, 256>>>(in_w, inwh,  inwm,  3 * DD * DD / 4);
    split_kernel<<<(DD * DD / 4 + 255) / 256, 256>>>(out_w,   outwh, outwm, DD * DD / 4);
    split_kernel<<<(DFF * DD / 4 + 255) / 256, 256>>>(w1,     w1h,   w1m,   DFF * DD / 4);
    split_kernel<<<(DD * DFF / 4 + 255) / 256, 256>>>(w2,     w2h,   w2m,   DD * DFF / 4);

    // 1. QKV projection (fp32 out)
    gemm_bf16x3<false, true, false><<<dim3(3 * DD / 128, MTOT / 128), 256, GEMM_SMEM>>>(
        xh, xm, inwh, inwm, in_b, qkv, nullptr, nullptr, MTOT, 3 * DD, DD);
    // 2. attention (split out)
    attn_kernel<<<dim3(SS / 32, HH, BB), 1024>>>(qkv, ath, atm);
    // 3. out_proj (fp32 out)
    gemm_bf16x3<false, true, false><<<dim3(DD / 128, MTOT / 128), 256, GEMM_SMEM>>>(
        ath, atm, outwh, outwm, out_b, tmp, nullptr, nullptr, MTOT, DD, DD);
    // 4. ln1 (fp32 + split out)
    ln_kernel<<<MTOT, 256>>>(x, tmp, ln1g, ln1b, x2, x2h, x2m);
    // 5. ffn1 (relu, split out)
    gemm_bf16x3<true, false, true><<<dim3(DFF / 128, MTOT / 128), 256, GEMM_SMEM>>>(
        x2h, x2m, w1h, w1m, b1, nullptr, ffh, ffm, MTOT, DFF, DD);
    // 6. ffn2 (fp32 out)
    gemm_bf16x3<false, true, false><<<dim3(DD / 128, MTOT / 128), 256, GEMM_SMEM>>>(
        ffh, ffm, w2h, w2m, b2, tmp, nullptr, nullptr, MTOT, DD, DFF);
    // 7. ln2 -> final out
    ln_kernel<<<MTOT, 256>>>(x2, tmp, ln2g, ln2b, out, nullptr, nullptr);
}

// round 4
// speedup vs baseline: 1.7281x; 1.0265x over previous
#include <cuda_runtime.h>
#include <cuda_bf16.h>
#include <math.h>
#include <stdint.h>

#define BB   2
#define SS   2048
#define DD   1024
#define HH   16
#define HD   64
#define DFF  4096
#define WIN  128
#define MTOT (BB * SS)

typedef __nv_bfloat16 bf16;

// ---------------- device scratch ----------------
__device__ float g_qkv[(size_t)MTOT * 3 * DD];
__device__ float g_tmp[(size_t)MTOT * DD];
__device__ float g_x2 [(size_t)MTOT * DD];
__device__ bf16 g_x_hi  [(size_t)MTOT * DD],  g_x_mid [(size_t)MTOT * DD];
__device__ bf16 g_inw_hi[(size_t)3*DD*DD],    g_inw_mid[(size_t)3*DD*DD];
__device__ bf16 g_outw_hi[(size_t)DD*DD],     g_outw_mid[(size_t)DD*DD];
__device__ bf16 g_w1_hi [(size_t)DFF*DD],     g_w1_mid[(size_t)DFF*DD];
__device__ bf16 g_w2_hi [(size_t)DD*DFF],     g_w2_mid[(size_t)DD*DFF];
__device__ bf16 g_attn_hi[(size_t)MTOT*DD],   g_attn_mid[(size_t)MTOT*DD];
__device__ bf16 g_x2_hi [(size_t)MTOT*DD],    g_x2_mid[(size_t)MTOT*DD];
__device__ bf16 g_ff_hi [(size_t)MTOT*DFF],   g_ff_mid[(size_t)MTOT*DFF];

// ---------------- low-level helpers (arch-agnostic PTX only) ----------------
__device__ __forceinline__ uint32_t smem_u32(const void* p) {
    uint32_t a;
    asm("{ .reg .u64 t; cvta.to.shared.u64 t, %1; cvt.u32.u64 %0, t; }" : "=r"(a) : "l"(p));
    return a;
}
__device__ __forceinline__ void cp16(uint32_t dst, const void* src) {
    asm volatile("cp.async.cg.shared.global [%0], [%1], 16;" :: "r"(dst), "l"(src));
}
__device__ __forceinline__ void cp_commit() {
    asm volatile("cp.async.commit_group;" ::: "memory");
}
template<int N>
__device__ __forceinline__ void cp_wait() {
    asm volatile("cp.async.wait_group %0;" :: "n"(N) : "memory");
}
__device__ __forceinline__ void mma_bf16(float& c0, float& c1, float& c2, float& c3,
                                         uint32_t a0, uint32_t a1, uint32_t a2, uint32_t a3,
                                         uint32_t b0, uint32_t b1) {
    asm volatile(
        "mma.sync.aligned.m16n8k16.row.col.f32.bf16.bf16.f32 "
        "{%0,%1,%2,%3}, {%4,%5,%6,%7}, {%8,%9}, {%0,%1,%2,%3};"
        : "+f"(c0), "+f"(c1), "+f"(c2), "+f"(c3)
        : "r"(a0), "r"(a1), "r"(a2), "r"(a3), "r"(b0), "r"(b1));
}
__device__ __forceinline__ void ldsm_x4(uint32_t& r0, uint32_t& r1, uint32_t& r2, uint32_t& r3,
                                        uint32_t addr) {
    asm volatile("ldmatrix.sync.aligned.m8n8.x4.shared.b16 {%0,%1,%2,%3}, [%4];"
                 : "=r"(r0), "=r"(r1), "=r"(r2), "=r"(r3) : "r"(addr));
}
__device__ __forceinline__ void ldsm_x2(uint32_t& r0, uint32_t& r1, uint32_t addr) {
    asm volatile("ldmatrix.sync.aligned.m8n8.x2.shared.b16 {%0,%1}, [%2];"
                 : "=r"(r0), "=r"(r1) : "r"(addr));
}

// ---------------- bf16x3 GEMM via mma.sync ----------------
// C[M,N] = A[M,K] @ B[N,K]^T + bias.  A,B are bf16 hi/mid splits.
// Block 256(M) x 128(N), BK=32, 512 thr, warp grid 4(m)x4(n), warp tile 64x32.
// Smem rows padded to 40 bf16 (80B): conflict-free for ldmatrix (8-row phases
// land on disjoint bank groups) and for cp.async stores.
#define PITCH   40
#define A_MAT   (256 * PITCH)              // 10240 elems
#define B_MAT   (128 * PITCH)              // 5120 elems
#define STAGE_E (2 * A_MAT + 2 * B_MAT)    // 30720 elems
#define GEMM_SMEM (2 * STAGE_E * 2)        // 122880 bytes

template<bool RELU, bool WF32, bool WSPLIT>
__global__ __launch_bounds__(512, 1)
void gemm_bf16x3(const bf16* __restrict__ Ahi, const bf16* __restrict__ Amid,
                 const bf16* __restrict__ Bhi, const bf16* __restrict__ Bmid,
                 const float* __restrict__ bias,
                 float* __restrict__ C, bf16* __restrict__ Chi, bf16* __restrict__ Cmid,
                 int M, int N, int K)
{
    extern __shared__ __align__(16) bf16 sm[];
    const uint32_t sbase = smem_u32(sm);
    const int tid  = threadIdx.x;
    const int warp = tid >> 5, lane = tid & 31;
    const int gid  = lane >> 2, tig = lane & 3;
    const int wm   = warp >> 2;          // 0..3
    const int wn   = warp & 3;           // 0..3
    const int bx = blockIdx.x, by = blockIdx.y;

    const size_t Abase = (size_t)(by * 256) * K;
    const size_t Bbase = (size_t)(bx * 128) * K;

    // stage loader: 3072 16B chunks, 6 per thread
    auto load_stage = [&](int chunk, int s) {
        const int k0 = chunk * 32;
        const uint32_t sb = sbase + s * (STAGE_E * 2);
#pragma unroll
        for (int i = 0; i < 6; i++) {
            int idx = i * 512 + tid;
            if (idx < 2048) {                       // A hi/mid
                int mat = idx >> 10, rem = idx & 1023;
                int r = rem >> 2, c16 = rem & 3;
                uint32_t dst = sb + (uint32_t)(mat * A_MAT + r * PITCH + c16 * 8) * 2;
                const bf16* srcp = (mat == 0) ? Ahi : Amid;
                cp16(dst, srcp + Abase + (size_t)r * K + k0 + c16 * 8);
            } else {                                // B hi/mid
                int j = idx - 2048;
                int mat = j >> 9, rem = j & 511;
                int r = rem >> 2, c16 = rem & 3;
                uint32_t dst = sb + (uint32_t)(2 * A_MAT + mat * B_MAT + r * PITCH + c16 * 8) * 2;
                const bf16* srcp = (mat == 0) ? Bhi : Bmid;
                cp16(dst, srcp + Bbase + (size_t)r * K + k0 + c16 * 8);
            }
        }
        cp_commit();
    };

    float acc[4][4][4];
#pragma unroll
    for (int i = 0; i < 4; i++)
#pragma unroll
        for (int j = 0; j < 4; j++)
#pragma unroll
            for (int v = 0; v < 4; v++) acc[i][j][v] = 0.f;

    // per-lane ldmatrix row offsets (elements)
    // A x4: lanes 0-15 -> rows (lane&15) at k+0 ; lanes 16-31 -> rows at k+8
    const uint32_t a_off = (uint32_t)((wm * 64 + (lane & 15)) * PITCH + (lane >> 4) * 8) * 2;
    // B x2: lanes 0-7 -> rows n0..n0+7 at k ; lanes 8-15 -> same rows at k+8
    const uint32_t b_off = (uint32_t)((wn * 32 + (lane & 7)) * PITCH + ((lane >> 3) & 1) * 8) * 2;

    const int nch = K >> 5;
    load_stage(0, 0);

    for (int c = 0; c < nch; c++) {
        const int s = c & 1;
        if (c + 1 < nch) { load_stage(c + 1, s ^ 1); cp_wait<1>(); }
        else             { cp_wait<0>(); }
        __syncthreads();

        const uint32_t st = sbase + s * (STAGE_E * 2);
        const uint32_t Ah = st;
        const uint32_t Am = st + A_MAT * 2;
        const uint32_t Bh = st + 2 * A_MAT * 2;
        const uint32_t Bm = st + (2 * A_MAT + B_MAT) * 2;

#pragma unroll
        for (int kk = 0; kk < 32; kk += 16) {
            const uint32_t kb = kk * 2;
            uint32_t bh[4][2], bm[4][2];
#pragma unroll
            for (int nt = 0; nt < 4; nt++) {
                const uint32_t bo = b_off + (uint32_t)(nt * 8 * PITCH) * 2 + kb;
                ldsm_x2(bh[nt][0], bh[nt][1], Bh + bo);
                ldsm_x2(bm[nt][0], bm[nt][1], Bm + bo);
            }
#pragma unroll
            for (int mt = 0; mt < 4; mt++) {
                const uint32_t ao = a_off + (uint32_t)(mt * 16 * PITCH) * 2 + kb;
                uint32_t a0, a1, a2, a3, e0, e1, e2, e3;
                ldsm_x4(a0, a1, a2, a3, Ah + ao);
                ldsm_x4(e0, e1, e2, e3, Am + ao);
#pragma unroll
                for (int nt = 0; nt < 4; nt++) {
                    float* a = acc[mt][nt];
                    mma_bf16(a[0], a[1], a[2], a[3], a0, a1, a2, a3, bh[nt][0], bh[nt][1]);
                    mma_bf16(a[0], a[1], a[2], a[3], a0, a1, a2, a3, bm[nt][0], bm[nt][1]);
                    mma_bf16(a[0], a[1], a[2], a[3], e0, e1, e2, e3, bh[nt][0], bh[nt][1]);
                }
            }
        }
        __syncthreads();
    }

    // epilogue
#pragma unroll
    for (int mt = 0; mt < 4; mt++) {
#pragma unroll
        for (int nt = 0; nt < 4; nt++) {
            const int col = bx * 128 + wn * 32 + nt * 8 + tig * 2;
            const float2 bv = *(const float2*)&bias[col];
            const int row0 = by * 256 + wm * 64 + mt * 16 + gid;
#pragma unroll
            for (int half = 0; half < 2; half++) {
                const int row = row0 + half * 8;
                float v0 = acc[mt][nt][half * 2]     + bv.x;
                float v1 = acc[mt][nt][half * 2 + 1] + bv.y;
                if (RELU) { v0 = fmaxf(v0, 0.f); v1 = fmaxf(v1, 0.f); }
                const size_t o = (size_t)row * N + col;
                if (WF32) *(float2*)(C + o) = make_float2(v0, v1);
                if (WSPLIT) {
                    bf16 h0 = __float2bfloat16(v0);
                    bf16 h1 = __float2bfloat16(v1);
                    __nv_bfloat162 hp; hp.x = h0; hp.y = h1;
                    __nv_bfloat162 mp;
                    mp.x = __float2bfloat16(v0 - __bfloat162float(h0));
                    mp.y = __float2bfloat16(v1 - __bfloat162float(h1));
                    *(__nv_bfloat162*)(Chi + o)  = hp;
                    *(__nv_bfloat162*)(Cmid + o) = mp;
                }
            }
        }
    }
}

// ---------------- fp32 -> (hi,mid) bf16 split ----------------
__global__ __launch_bounds__(256)
void split_kernel(const float* __restrict__ src, bf16* __restrict__ hi,
                  bf16* __restrict__ mid, int n4)
{
    int i = blockIdx.x * 256 + threadIdx.x;
    if (i >= n4) return;
    float4 v = ((const float4*)src)[i];
    bf16 h0 = __float2bfloat16(v.x), h1 = __float2bfloat16(v.y);
    bf16 h2 = __float2bfloat16(v.z), h3 = __float2bfloat16(v.w);
    __nv_bfloat162 a, b, c, d;
    a.x = h0; a.y = h1; b.x = h2; b.y = h3;
    c.x = __float2bfloat16(v.x - __bfloat162float(h0));
    c.y = __float2bfloat16(v.y - __bfloat162float(h1));
    d.x = __float2bfloat16(v.z - __bfloat162float(h2));
    d.y = __float2bfloat16(v.w - __bfloat162float(h3));
    ((__nv_bfloat162*)hi)[i*2]     = a;
    ((__nv_bfloat162*)hi)[i*2+1]   = b;
    ((__nv_bfloat162*)mid)[i*2]    = c;
    ((__nv_bfloat162*)mid)[i*2+1]  = d;
}

// ---------------- banded flash attention (fp32 in, split out) ----------------
__global__ __launch_bounds__(1024)
void attn_kernel(const float* __restrict__ qkv,
                 bf16* __restrict__ out_hi, bf16* __restrict__ out_mid)
{
    const int b  = blockIdx.z;
    const int h  = blockIdx.y;
    const int q0 = blockIdx.x * 32;
    const int warp = threadIdx.x >> 5;
    const int lane = threadIdx.x & 31;
    const int q = q0 + warp;

    const float* base = qkv + (size_t)b * SS * (3 * DD);
    const int hc = h * HD;

    const float q0r = base[(size_t)q * (3 * DD) + hc + lane];
    const float q1r = base[(size_t)q * (3 * DD) + hc + lane + 32];

    const int klo = max(q0 - WIN, 0);
    const int khi = min(q0 + 31 + WIN, SS - 1);

    __shared__ float Ks[32][64];
    __shared__ float Vs[32][64];

    float m = -1e30f, lsum = 0.f, acc0 = 0.f, acc1 = 0.f;

    for (int c = klo; c <= khi; c += 32) {
        const int nk = min(32, khi - c + 1);
        __syncthreads();
        for (int idx = threadIdx.x; idx < nk * 64; idx += 1024) {
            int j = idx >> 6, d = idx & 63;
            size_t row = (size_t)(c + j) * (3 * DD);
            Ks[j][d] = base[row + DD + hc + d];
            Vs[j][d] = base[row + 2 * DD + hc + d];
        }
        __syncthreads();

        const int jlo = max(q - WIN, c) - c;
        const int jhi = min(q + WIN, c + nk - 1) - c;
        for (int j = jlo; j <= jhi; j++) {
            float partial = q0r * Ks[j][lane] + q1r * Ks[j][lane + 32];
#pragma unroll
            for (int off = 16; off > 0; off >>= 1)
                partial += __shfl_xor_sync(0xFFFFFFFFu, partial, off);
            float s = partial * 0.125f;
            float nm = fmaxf(m, s);
            float scale = __expf(m - nm);
            float p = __expf(s - nm);
            lsum = lsum * scale + p;
            acc0 = acc0 * scale + p * Vs[j][lane];
            acc1 = acc1 * scale + p * Vs[j][lane + 32];
            m = nm;
        }
    }

    const float inv = 1.f / lsum;
    const float v0 = acc0 * inv, v1 = acc1 * inv;
    const size_t ob = ((size_t)b * SS + q) * DD + hc;
    bf16 h0 = __float2bfloat16(v0), h1 = __float2bfloat16(v1);
    out_hi[ob + lane]       = h0;
    out_hi[ob + lane + 32]  = h1;
    out_mid[ob + lane]      = __float2bfloat16(v0 - __bfloat162float(h0));
    out_mid[ob + lane + 32] = __float2bfloat16(v1 - __bfloat162float(h1));
}

// ---------------- fused residual + LayerNorm (+ optional split out) ----------------
__global__ __launch_bounds__(256)
void ln_kernel(const float* __restrict__ A, const float* __restrict__ R,
               const float* __restrict__ g, const float* __restrict__ be,
               float* __restrict__ out, bf16* __restrict__ ohi, bf16* __restrict__ omid)
{
    const int row = blockIdx.x;
    const int t = threadIdx.x;
    const size_t base = (size_t)row * DD;

    float4 av = *(const float4*)(A + base + t * 4);
    float4 rv = *(const float4*)(R + base + t * 4);
    float4 v = make_float4(av.x + rv.x, av.y + rv.y, av.z + rv.z, av.w + rv.w);

    float s = v.x + v.y + v.z + v.w;
    float q = v.x * v.x + v.y * v.y + v.z * v.z + v.w * v.w;
#pragma unroll
    for (int off = 16; off > 0; off >>= 1) {
        s += __shfl_xor_sync(0xFFFFFFFFu, s, off);
        q += __shfl_xor_sync(0xFFFFFFFFu, q, off);
    }
    __shared__ float ss[8], sq[8];
    __shared__ float mu_s, inv_s;
    if ((t & 31) == 0) { ss[t >> 5] = s; sq[t >> 5] = q; }
    __syncthreads();
    if (t == 0) {
        float S = 0.f, Q = 0.f;
#pragma unroll
        for (int i = 0; i < 8; i++) { S += ss[i]; Q += sq[i]; }
        float mu = S * (1.f / DD);
        float var = Q * (1.f / DD) - mu * mu;
        mu_s = mu;
        inv_s = rsqrtf(var + 1e-5f);
    }
    __syncthreads();
    const float mu = mu_s, inv = inv_s;

    float4 gv = *(const float4*)(g + t * 4);
    float4 bv = *(const float4*)(be + t * 4);
    float4 o;
    o.x = (v.x - mu) * inv * gv.x + bv.x;
    o.y = (v.y - mu) * inv * gv.y + bv.y;
    o.z = (v.z - mu) * inv * gv.z + bv.z;
    o.w = (v.w - mu) * inv * gv.w + bv.w;
    *(float4*)(out + base + t * 4) = o;

    if (ohi != nullptr) {
        bf16 h0 = __float2bfloat16(o.x), h1 = __float2bfloat16(o.y);
        bf16 h2 = __float2bfloat16(o.z), h3 = __float2bfloat16(o.w);
        __nv_bfloat162 p0, p1, m0, m1;
        p0.x = h0; p0.y = h1; p1.x = h2; p1.y = h3;
        m0.x = __float2bfloat16(o.x - __bfloat162float(h0));
        m0.y = __float2bfloat16(o.y - __bfloat162float(h1));
        m1.x = __float2bfloat16(o.z - __bfloat162float(h2));
        m1.y = __float2bfloat16(o.w - __bfloat162float(h3));
        *(__nv_bfloat162*)(ohi + base + t * 4)      = p0;
        *(__nv_bfloat162*)(ohi + base + t * 4 + 2)  = p1;
        *(__nv_bfloat162*)(omid + base + t * 4)     = m0;
        *(__nv_bfloat162*)(omid + base + t * 4 + 2) = m1;
    }
}

// ---------------- host ----------------
extern "C" void kernel_launch(void* const* d_in, const int* in_sizes, int n_in,
                              void* d_out, int out_size)
{
    (void)in_sizes; (void)n_in; (void)out_size;
    const float* x     = (const float*)d_in[0];
    const float* in_w  = (const float*)d_in[1];
    const float* in_b  = (const float*)d_in[2];
    const float* out_w = (const float*)d_in[3];
    const float* out_b = (const float*)d_in[4];
    const float* ln1g  = (const float*)d_in[5];
    const float* ln1b  = (const float*)d_in[6];
    const float* w1    = (const float*)d_in[7];
    const float* b1    = (const float*)d_in[8];
    const float* w2    = (const float*)d_in[9];
    const float* b2    = (const float*)d_in[10];
    const float* ln2g  = (const float*)d_in[11];
    const float* ln2b  = (const float*)d_in[12];
    float* out = (float*)d_out;

    float *qkv, *tmp, *x2;
    bf16 *xh, *xm, *inwh, *inwm, *outwh, *outwm, *w1h, *w1m, *w2h, *w2m;
    bf16 *ath, *atm, *x2h, *x2m, *ffh, *ffm;
    cudaGetSymbolAddress((void**)&qkv,   g_qkv);
    cudaGetSymbolAddress((void**)&tmp,   g_tmp);
    cudaGetSymbolAddress((void**)&x2,    g_x2);
    cudaGetSymbolAddress((void**)&xh,    g_x_hi);    cudaGetSymbolAddress((void**)&xm,    g_x_mid);
    cudaGetSymbolAddress((void**)&inwh,  g_inw_hi);  cudaGetSymbolAddress((void**)&inwm,  g_inw_mid);
    cudaGetSymbolAddress((void**)&outwh, g_outw_hi); cudaGetSymbolAddress((void**)&outwm, g_outw_mid);
    cudaGetSymbolAddress((void**)&w1h,   g_w1_hi);   cudaGetSymbolAddress((void**)&w1m,   g_w1_mid);
    cudaGetSymbolAddress((void**)&w2h,   g_w2_hi);   cudaGetSymbolAddress((void**)&w2m,   g_w2_mid);
    cudaGetSymbolAddress((void**)&ath,   g_attn_hi); cudaGetSymbolAddress((void**)&atm,   g_attn_mid);
    cudaGetSymbolAddress((void**)&x2h,   g_x2_hi);   cudaGetSymbolAddress((void**)&x2m,   g_x2_mid);
    cudaGetSymbolAddress((void**)&ffh,   g_ff_hi);   cudaGetSymbolAddress((void**)&ffm,   g_ff_mid);

    cudaFuncSetAttribute(gemm_bf16x3<false, true, false>,
                         cudaFuncAttributeMaxDynamicSharedMemorySize, GEMM_SMEM);
    cudaFuncSetAttribute(gemm_bf16x3<true, false, true>,
                         cudaFuncAttributeMaxDynamicSharedMemorySize, GEMM_SMEM);

    // splits of raw inputs
    split_kernel<<<(MTOT * DD / 4 + 255) / 256, 256>>>(x,     xh,    xm,    MTOT * DD / 4);
    split_kernel<<<(3 * DD * DD / 4 + 255) / 256, 256>>>(in_w, inwh,  inwm,  3 * DD * DD / 4);
    split_kernel<<<(DD * DD / 4 + 255) / 256, 256>>>(out_w,   outwh, outwm, DD * DD / 4);
    split_kernel<<<(DFF * DD / 4 + 255) / 256, 256>>>(w1,     w1h,   w1m,   DFF * DD / 4);
    split_kernel<<<(DD * DFF / 4 + 255) / 256, 256>>>(w2,     w2h,   w2m,   DD * DFF / 4);

    // 1. QKV projection (fp32 out)
    gemm_bf16x3<false, true, false><<<dim3(3 * DD / 128, MTOT / 256), 512, GEMM_SMEM>>>(
        xh, xm, inwh, inwm, in_b, qkv, nullptr, nullptr, MTOT, 3 * DD, DD);
    // 2. attention (split out)
    attn_kernel<<<dim3(SS / 32, HH, BB), 1024>>>(qkv, ath, atm);
    // 3. out_proj (fp32 out)
    gemm_bf16x3<false, true, false><<<dim3(DD / 128, MTOT / 256), 512, GEMM_SMEM>>>(
        ath, atm, outwh, outwm, out_b, tmp, nullptr, nullptr, MTOT, DD, DD);
    // 4. ln1 (fp32 + split out)
    ln_kernel<<<MTOT, 256>>>(x, tmp, ln1g, ln1b, x2, x2h, x2m);
    // 5. ffn1 (relu, split out)
    gemm_bf16x3<true, false, true><<<dim3(DFF / 128, MTOT / 256), 512, GEMM_SMEM>>>(
        x2h, x2m, w1h, w1m, b1, nullptr, ffh, ffm, MTOT, DFF, DD);
    // 6. ffn2 (fp32 out)
    gemm_bf16x3<false, true, false><<<dim3(DD / 128, MTOT / 256), 512, GEMM_SMEM>>>(
        ffh, ffm, w2h, w2m, b2, tmp, nullptr, nullptr, MTOT, DD, DFF);
    // 7. ln2 -> final out
    ln_kernel<<<MTOT, 256>>>(x2, tmp, ln2g, ln2b, out, nullptr, nullptr);
}